// round 5
// baseline (speedup 1.0000x reference)
#include <cuda_runtime.h>
#include <math.h>

typedef unsigned long long ull;

// Problem constants
static constexpr int B = 64;
static constexpr int T = 512;
static constexpr int I = 1024;
static constexpr int H = 1024;
static constexpr int G4H = 4 * H;   // 4096

static constexpr int NCTA = 128;
static constexpr int NTHR = 512;

// Scratch in device globals (no allocation allowed)
__device__ float g_xproj[(size_t)T * B * G4H];  // [T][B][4H]
__device__ float g_h[2][B * H];                 // h ping-pong
__device__ unsigned g_bar_count = 0;
__device__ unsigned g_bar_sense = 0;

// ---------------------------------------------------------------------------
// f32x2 packed-FMA helpers
// ---------------------------------------------------------------------------
__device__ __forceinline__ ull dup2(float x) {
    ull r; asm("mov.b64 %0, {%1, %1};" : "=l"(r) : "f"(x)); return r;
}
__device__ __forceinline__ ull pack2(float x, float y) {
    ull r; asm("mov.b64 %0, {%1, %2};" : "=l"(r) : "f"(x), "f"(y)); return r;
}
__device__ __forceinline__ void fma2(ull& d, ull a, ull b) {
    asm("fma.rn.f32x2 %0, %1, %2, %0;" : "+l"(d) : "l"(a), "l"(b));
}
__device__ __forceinline__ float2 unpack2(ull v) {
    float2 f; asm("mov.b64 {%0, %1}, %2;" : "=f"(f.x), "=f"(f.y) : "l"(v)); return f;
}
__device__ __forceinline__ ull d2l(double d) { return __double_as_longlong(d); }

__device__ __forceinline__ float fast_tanh(float x) {
    float y; asm("tanh.approx.f32 %0, %1;" : "=f"(y) : "f"(x)); return y;
}
__device__ __forceinline__ float fast_sigmoid(float x) {
    return 0.5f * fast_tanh(0.5f * x) + 0.5f;
}

// ---------------------------------------------------------------------------
// init: zero h[0]
// ---------------------------------------------------------------------------
__global__ void init_kernel() {
    int i = blockIdx.x * blockDim.x + threadIdx.x;
    if (i < B * H) g_h[0][i] = 0.0f;
}

// ---------------------------------------------------------------------------
// xproj GEMM (unchanged): C = x @ Wx + b, scattered to [t][b][4H]
// ---------------------------------------------------------------------------
static constexpr int BM = 128;
static constexpr int BN = 128;
static constexpr int BK = 16;

__global__ void __launch_bounds__(256) xproj_kernel(
    const float* __restrict__ x,
    const float* __restrict__ w0, const float* __restrict__ w1,
    const float* __restrict__ w2, const float* __restrict__ w3,
    const float* __restrict__ b0, const float* __restrict__ b1,
    const float* __restrict__ b2, const float* __restrict__ b3)
{
    const int tid = threadIdx.x;
    const int m0 = blockIdx.y * BM;
    const int n0 = blockIdx.x * BN;
    const int gate = n0 >> 10;
    const float* __restrict__ w = (gate == 0) ? w0 : (gate == 1) ? w1 : (gate == 2) ? w2 : w3;
    const float* __restrict__ bias = (gate == 0) ? b0 : (gate == 1) ? b1 : (gate == 2) ? b2 : b3;
    const int j0 = n0 & (H - 1);

    __shared__ float As[BK][BM + 4];
    __shared__ float Bs[BK][BN + 4];

    const int tx = tid & 15;
    const int ty = tid >> 4;

    ull acc[4][8];
    #pragma unroll
    for (int i = 0; i < 4; ++i)
        #pragma unroll
        for (int j = 0; j < 8; ++j) acc[i][j] = 0ULL;

    const int ar = tid >> 2;
    const int ak = (tid & 3) * 4;
    const int bk = tid >> 5;
    const int bc = (tid & 31) * 4;

    for (int k0 = 0; k0 < I; k0 += BK) {
        #pragma unroll
        for (int p = 0; p < 2; ++p) {
            int r = ar + p * 64;
            float4 v = *reinterpret_cast<const float4*>(&x[(size_t)(m0 + r) * I + k0 + ak]);
            As[ak + 0][r] = v.x;
            As[ak + 1][r] = v.y;
            As[ak + 2][r] = v.z;
            As[ak + 3][r] = v.w;
        }
        #pragma unroll
        for (int p = 0; p < 2; ++p) {
            int kk = bk + p * 8;
            float4 v = *reinterpret_cast<const float4*>(&w[(size_t)(k0 + kk) * H + j0 + bc]);
            *reinterpret_cast<float4*>(&Bs[kk][bc]) = v;
        }
        __syncthreads();

        #pragma unroll
        for (int kk = 0; kk < BK; ++kk) {
            double2 da = *reinterpret_cast<const double2*>(&As[kk][ty * 8]);
            double2 db = *reinterpret_cast<const double2*>(&As[kk][ty * 8 + 4]);
            ull arw[4] = {d2l(da.x), d2l(da.y), d2l(db.x), d2l(db.y)};
            float4 c0 = *reinterpret_cast<const float4*>(&Bs[kk][tx * 8]);
            float4 c1 = *reinterpret_cast<const float4*>(&Bs[kk][tx * 8 + 4]);
            float bf_[8] = {c0.x, c0.y, c0.z, c0.w, c1.x, c1.y, c1.z, c1.w};
            #pragma unroll
            for (int j = 0; j < 8; ++j) {
                ull bj = dup2(bf_[j]);
                #pragma unroll
                for (int i = 0; i < 4; ++i)
                    fma2(acc[i][j], arw[i], bj);
            }
        }
        __syncthreads();
    }

    #pragma unroll
    for (int i2 = 0; i2 < 4; ++i2) {
        #pragma unroll
        for (int half = 0; half < 2; ++half) {
            int m = m0 + ty * 8 + i2 * 2 + half;
            int t = m & (T - 1);
            int bi_ = m >> 9;
            size_t base = ((size_t)t * B + bi_) * G4H + n0;
            #pragma unroll
            for (int j = 0; j < 8; ++j) {
                float2 u = unpack2(acc[i2][j]);
                float v = half ? u.y : u.x;
                int n = tx * 8 + j;
                g_xproj[base + n] = v + bias[j0 + n];
            }
        }
    }
}

// ---------------------------------------------------------------------------
// Persistent LSTM recurrence v2 — k-pair packed operands.
//
// 128 CTAs x 512 threads, 1 CTA/SM. CTA cg owns fused cols [gate*8 + cg*8..+8)
// (32 fc), all 64 rows, all T steps.
//
// SMEM:
//   ws  [512 kp][34 ull]  : Wh pre-packed, ws[kp][fc] = (w[2kp][fc], w[2kp+1][fc])
//   hs  [2][64 kp][66 f2] : h chunk (128 k), hs[kp][row] = (h[2kp][row], h[2kp+1][row])
//   gt  [64][36]          : gate accumulation
//
// Thread map: rg = tid&7 (8 row-groups), fcg = (tid>>3)&15 (16 fc-pairs),
//             ko = tid>>7 (4 k-slices within chunk).
// Thread rows: {2rg+16i, 2rg+16i+1}, i=0..3. Thread fc: {2fcg, 2fcg+1}.
// Per k-pair: 4x LDS.128 (a) + 1x LDS.128 (b) + 16 FFMA2, no packing instrs.
// ---------------------------------------------------------------------------
static constexpr int WS_STRIDE = 34;                         // ull per kp
static constexpr int WS_BYTES = 512 * WS_STRIDE * 8;         // 139264
static constexpr int HS_STRIDE = 66;                         // float2 per kp row
static constexpr int HS_CHUNK_F2 = 64 * HS_STRIDE;           // 4224
static constexpr int HS_BYTES = 2 * HS_CHUNK_F2 * 8;         // 67584
static constexpr int GT_STRIDE = 36;
static constexpr int GT_BYTES = 64 * GT_STRIDE * 4;          // 9216
static constexpr size_t SMEM_BYTES = WS_BYTES + HS_BYTES + GT_BYTES; // 216064

__global__ void __launch_bounds__(NTHR, 1) lstm_persistent(
    const float* __restrict__ wh0, const float* __restrict__ wh1,
    const float* __restrict__ wh2, const float* __restrict__ wh3,
    float* __restrict__ out)
{
    extern __shared__ char smem_raw[];
    ull*    ws = reinterpret_cast<ull*>(smem_raw);
    float2* hs = reinterpret_cast<float2*>(smem_raw + WS_BYTES);
    float*  gt = reinterpret_cast<float*>(smem_raw + WS_BYTES + HS_BYTES);
    __shared__ unsigned s_sense;

    const int tid = threadIdx.x;
    const int cg = blockIdx.x;
    const int j0 = cg * 8;

    const int rg  = tid & 7;
    const int fcg = (tid >> 3) & 15;
    const int ko  = tid >> 7;

    // ---- prepack Wh into ws (k-pair packed), once ----
    for (int idx = tid; idx < 512 * 8; idx += NTHR) {
        int kp = idx >> 3;
        int q = idx & 7;                  // fc quad: fc = q*4 + m
        int gate = q >> 1;
        int jj4 = (q & 1) * 4;
        const float* __restrict__ wsel = (gate == 0) ? wh0 : (gate == 1) ? wh1
                                       : (gate == 2) ? wh2 : wh3;
        float4 r0 = *reinterpret_cast<const float4*>(&wsel[(size_t)(2 * kp) * H + j0 + jj4]);
        float4 r1 = *reinterpret_cast<const float4*>(&wsel[(size_t)(2 * kp + 1) * H + j0 + jj4]);
        ull* dst = ws + (size_t)kp * WS_STRIDE + q * 4;
        dst[0] = pack2(r0.x, r1.x);
        dst[1] = pack2(r0.y, r1.y);
        dst[2] = pack2(r0.z, r1.z);
        dst[3] = pack2(r0.w, r1.w);
    }
    if (tid == 0) s_sense = 0;
    __syncthreads();

    const int prow = tid >> 3;            // pointwise ownership
    const int pjj = tid & 7;
    float creg = 0.0f;

    const int srow = tid >> 3;            // staging: row
    const int skl = tid & 7;              // staging: k lane

    for (int t = 0; t < T; ++t) {
        const float* __restrict__ hin = g_h[t & 1];
        float* __restrict__ hout = g_h[(t + 1) & 1];

        // xproj prefetch (ko==0 threads own the gt store)
        float2 xp[4][2];
        if (ko == 0) {
            int gate = fcg >> 2;
            int jj = (fcg * 2) & 7;
            size_t base = (size_t)t * B * G4H + (size_t)gate * H + j0 + jj;
            #pragma unroll
            for (int i = 0; i < 4; ++i)
                #pragma unroll
                for (int p = 0; p < 2; ++p) {
                    int r = 2 * rg + 16 * i + p;
                    xp[i][p] = *reinterpret_cast<const float2*>(&g_xproj[base + (size_t)r * G4H]);
                }
        }

        // stage chunk 0 (k-pair packed, transposed)
        #pragma unroll
        for (int u = 0; u < 4; ++u) {
            int klocal = skl * 4 + u * 32;
            float4 v = __ldcg(reinterpret_cast<const float4*>(&hin[srow * H + klocal]));
            int kp = klocal >> 1;
            hs[(size_t)kp * HS_STRIDE + srow]       = make_float2(v.x, v.y);
            hs[(size_t)(kp + 1) * HS_STRIDE + srow] = make_float2(v.z, v.w);
        }
        __syncthreads();

        ull acc[4][2][2];
        #pragma unroll
        for (int i = 0; i < 4; ++i) {
            acc[i][0][0] = 0; acc[i][0][1] = 0; acc[i][1][0] = 0; acc[i][1][1] = 0;
        }

        for (int c = 0; c < 8; ++c) {
            // prefetch chunk c+1 into registers
            float4 pf[4];
            if (c + 1 < 8) {
                #pragma unroll
                for (int u = 0; u < 4; ++u) {
                    int kglob = (c + 1) * 128 + skl * 4 + u * 32;
                    pf[u] = __ldcg(reinterpret_cast<const float4*>(&hin[srow * H + kglob]));
                }
            }

            const float2* hb = hs + (c & 1) * HS_CHUNK_F2;
            const ull* wb = ws + (size_t)(c * 64 + ko * 16) * WS_STRIDE + fcg * 2;
            const int kpb = ko * 16;

            #pragma unroll
            for (int q = 0; q < 16; ++q) {
                longlong2 b2 = *reinterpret_cast<const longlong2*>(wb + (size_t)q * WS_STRIDE);
                const float2* hrow = hb + (size_t)(kpb + q) * HS_STRIDE + 2 * rg;
                ull bx = (ull)b2.x, by = (ull)b2.y;
                #pragma unroll
                for (int i = 0; i < 4; ++i) {
                    longlong2 a = *reinterpret_cast<const longlong2*>(hrow + 16 * i);
                    ull ax = (ull)a.x, ay = (ull)a.y;
                    fma2(acc[i][0][0], ax, bx);
                    fma2(acc[i][0][1], ax, by);
                    fma2(acc[i][1][0], ay, bx);
                    fma2(acc[i][1][1], ay, by);
                }
            }

            if (c + 1 < 8) {
                float2* hn = hs + ((c + 1) & 1) * HS_CHUNK_F2;
                #pragma unroll
                for (int u = 0; u < 4; ++u) {
                    int kp = (skl * 4 + u * 32) >> 1;
                    hn[(size_t)kp * HS_STRIDE + srow]       = make_float2(pf[u].x, pf[u].y);
                    hn[(size_t)(kp + 1) * HS_STRIDE + srow] = make_float2(pf[u].z, pf[u].w);
                }
            }
            __syncthreads();
        }

        // ---- k-split reduction into gt (ko0 stores, ko1..3 sequential RMW) ----
        if (ko == 0) {
            #pragma unroll
            for (int i = 0; i < 4; ++i)
                #pragma unroll
                for (int p = 0; p < 2; ++p) {
                    int r = 2 * rg + 16 * i + p;
                    float2 u0 = unpack2(acc[i][p][0]);
                    float2 u1 = unpack2(acc[i][p][1]);
                    gt[r * GT_STRIDE + fcg * 2 + 0] = u0.x + u0.y + xp[i][p].x;
                    gt[r * GT_STRIDE + fcg * 2 + 1] = u1.x + u1.y + xp[i][p].y;
                }
        }
        __syncthreads();
        #pragma unroll
        for (int pass = 1; pass <= 3; ++pass) {
            if (ko == pass) {
                #pragma unroll
                for (int i = 0; i < 4; ++i)
                    #pragma unroll
                    for (int p = 0; p < 2; ++p) {
                        int r = 2 * rg + 16 * i + p;
                        float2 u0 = unpack2(acc[i][p][0]);
                        float2 u1 = unpack2(acc[i][p][1]);
                        gt[r * GT_STRIDE + fcg * 2 + 0] += u0.x + u0.y;
                        gt[r * GT_STRIDE + fcg * 2 + 1] += u1.x + u1.y;
                    }
            }
            __syncthreads();
        }

        // ---- pointwise LSTM cell: one element per thread ----
        {
            float gi = gt[prow * GT_STRIDE + 0 + pjj];
            float gf = gt[prow * GT_STRIDE + 8 + pjj];
            float gg = gt[prow * GT_STRIDE + 16 + pjj];
            float go = gt[prow * GT_STRIDE + 24 + pjj];
            float ig = fast_sigmoid(gi);
            float fg = fast_sigmoid(gf);
            float gv = fast_tanh(gg);
            float og = fast_sigmoid(go);
            creg = fg * creg + ig * gv;
            float hv = og * fast_tanh(creg);
            int j = j0 + pjj;
            hout[prow * H + j] = hv;
            out[((size_t)prow * T + t) * H + j] = hv;
            if (t == T - 1) {
                size_t off = (size_t)B * T * H;
                out[off + (size_t)prow * H + j] = hv;
                out[off + (size_t)B * H + (size_t)prow * H + j] = creg;
            }
        }

        // ---- grid barrier (fence only in thread 0, after CTA-wide bar) ----
        __syncthreads();
        if (tid == 0) {
            __threadfence();
            unsigned s = s_sense ^ 1u;
            s_sense = s;
            if (atomicAdd(&g_bar_count, 1u) == NCTA - 1u) {
                g_bar_count = 0;
                asm volatile("st.release.gpu.global.u32 [%0], %1;"
                             :: "l"(&g_bar_sense), "r"(s) : "memory");
            } else {
                unsigned v;
                while (true) {
                    asm volatile("ld.acquire.gpu.global.u32 %0, [%1];"
                                 : "=r"(v) : "l"(&g_bar_sense) : "memory");
                    if (v == s) break;
                    __nanosleep(32);
                }
            }
        }
        __syncthreads();
    }
}

// ---------------------------------------------------------------------------
extern "C" void kernel_launch(void* const* d_in, const int* in_sizes, int n_in,
                              void* d_out, int out_size)
{
    const float* x   = (const float*)d_in[0];
    const float* wii = (const float*)d_in[1];
    const float* whi = (const float*)d_in[2];
    const float* bi  = (const float*)d_in[3];
    const float* wif = (const float*)d_in[4];
    const float* whf = (const float*)d_in[5];
    const float* bf  = (const float*)d_in[6];
    const float* wig = (const float*)d_in[7];
    const float* whg = (const float*)d_in[8];
    const float* bg  = (const float*)d_in[9];
    const float* wio = (const float*)d_in[10];
    const float* who = (const float*)d_in[11];
    const float* bo  = (const float*)d_in[12];
    float* out = (float*)d_out;

    cudaFuncSetAttribute(lstm_persistent,
                         cudaFuncAttributeMaxDynamicSharedMemorySize,
                         (int)SMEM_BYTES);

    init_kernel<<<(B * H + 255) / 256, 256>>>();

    dim3 gx(G4H / BN, (B * T) / BM);   // (32, 256)
    xproj_kernel<<<gx, 256>>>(x, wii, wif, wig, wio, bi, bf, bg, bo);

    lstm_persistent<<<NCTA, NTHR, SMEM_BYTES>>>(whi, whf, whg, who, out);
}

// round 6
// speedup vs baseline: 1.2310x; 1.2310x over previous
#include <cuda_runtime.h>
#include <math.h>

typedef unsigned long long ull;

// Problem constants
static constexpr int B = 64;
static constexpr int T = 512;
static constexpr int I = 1024;
static constexpr int H = 1024;
static constexpr int G4H = 4 * H;   // 4096

static constexpr int NCTA = 128;
static constexpr int NTHR = 512;

// Scratch in device globals (no allocation allowed)
__device__ float g_xproj[(size_t)T * B * G4H];  // [T][B][4H]
__device__ float g_h[2][B * H];                 // h ping-pong
__device__ unsigned g_bar_count = 0;
__device__ unsigned g_bar_sense = 0;

// ---------------------------------------------------------------------------
// f32x2 packed-FMA helpers
// ---------------------------------------------------------------------------
__device__ __forceinline__ ull dup2(float x) {
    ull r; asm("mov.b64 %0, {%1, %1};" : "=l"(r) : "f"(x)); return r;
}
__device__ __forceinline__ void fma2(ull& d, ull a, ull b) {
    asm("fma.rn.f32x2 %0, %1, %2, %0;" : "+l"(d) : "l"(a), "l"(b));
}
__device__ __forceinline__ float2 unpack2(ull v) {
    float2 f; asm("mov.b64 {%0, %1}, %2;" : "=f"(f.x), "=f"(f.y) : "l"(v)); return f;
}
__device__ __forceinline__ ull d2l(double d) { return __double_as_longlong(d); }

__device__ __forceinline__ float fast_tanh(float x) {
    float y; asm("tanh.approx.f32 %0, %1;" : "=f"(y) : "f"(x)); return y;
}
__device__ __forceinline__ float fast_sigmoid(float x) {
    return 0.5f * fast_tanh(0.5f * x) + 0.5f;
}

// ---------------------------------------------------------------------------
// init: zero h[0]
// ---------------------------------------------------------------------------
__global__ void init_kernel() {
    int i = blockIdx.x * blockDim.x + threadIdx.x;
    if (i < B * H) g_h[0][i] = 0.0f;
}

// ---------------------------------------------------------------------------
// xproj GEMM (unchanged): C = x @ Wx + b, scattered to [t][b][4H]
// ---------------------------------------------------------------------------
static constexpr int BM = 128;
static constexpr int BN = 128;
static constexpr int BK = 16;

__device__ __forceinline__ ull dup2x(float x) { return dup2(x); }

__global__ void __launch_bounds__(256) xproj_kernel(
    const float* __restrict__ x,
    const float* __restrict__ w0, const float* __restrict__ w1,
    const float* __restrict__ w2, const float* __restrict__ w3,
    const float* __restrict__ b0, const float* __restrict__ b1,
    const float* __restrict__ b2, const float* __restrict__ b3)
{
    const int tid = threadIdx.x;
    const int m0 = blockIdx.y * BM;
    const int n0 = blockIdx.x * BN;
    const int gate = n0 >> 10;
    const float* __restrict__ w = (gate == 0) ? w0 : (gate == 1) ? w1 : (gate == 2) ? w2 : w3;
    const float* __restrict__ bias = (gate == 0) ? b0 : (gate == 1) ? b1 : (gate == 2) ? b2 : b3;
    const int j0 = n0 & (H - 1);

    __shared__ float As[BK][BM + 4];
    __shared__ float Bs[BK][BN + 4];

    const int tx = tid & 15;
    const int ty = tid >> 4;

    ull acc[4][8];
    #pragma unroll
    for (int i = 0; i < 4; ++i)
        #pragma unroll
        for (int j = 0; j < 8; ++j) acc[i][j] = 0ULL;

    const int ar = tid >> 2;
    const int ak = (tid & 3) * 4;
    const int bk = tid >> 5;
    const int bc = (tid & 31) * 4;

    for (int k0 = 0; k0 < I; k0 += BK) {
        #pragma unroll
        for (int p = 0; p < 2; ++p) {
            int r = ar + p * 64;
            float4 v = *reinterpret_cast<const float4*>(&x[(size_t)(m0 + r) * I + k0 + ak]);
            As[ak + 0][r] = v.x;
            As[ak + 1][r] = v.y;
            As[ak + 2][r] = v.z;
            As[ak + 3][r] = v.w;
        }
        #pragma unroll
        for (int p = 0; p < 2; ++p) {
            int kk = bk + p * 8;
            float4 v = *reinterpret_cast<const float4*>(&w[(size_t)(k0 + kk) * H + j0 + bc]);
            *reinterpret_cast<float4*>(&Bs[kk][bc]) = v;
        }
        __syncthreads();

        #pragma unroll
        for (int kk = 0; kk < BK; ++kk) {
            double2 da = *reinterpret_cast<const double2*>(&As[kk][ty * 8]);
            double2 db = *reinterpret_cast<const double2*>(&As[kk][ty * 8 + 4]);
            ull arw[4] = {d2l(da.x), d2l(da.y), d2l(db.x), d2l(db.y)};
            float4 c0 = *reinterpret_cast<const float4*>(&Bs[kk][tx * 8]);
            float4 c1 = *reinterpret_cast<const float4*>(&Bs[kk][tx * 8 + 4]);
            float bf_[8] = {c0.x, c0.y, c0.z, c0.w, c1.x, c1.y, c1.z, c1.w};
            #pragma unroll
            for (int j = 0; j < 8; ++j) {
                ull bj = dup2x(bf_[j]);
                #pragma unroll
                for (int i = 0; i < 4; ++i)
                    fma2(acc[i][j], arw[i], bj);
            }
        }
        __syncthreads();
    }

    #pragma unroll
    for (int i2 = 0; i2 < 4; ++i2) {
        #pragma unroll
        for (int half = 0; half < 2; ++half) {
            int m = m0 + ty * 8 + i2 * 2 + half;
            int t = m & (T - 1);
            int bi_ = m >> 9;
            size_t base = ((size_t)t * B + bi_) * G4H + n0;
            #pragma unroll
            for (int j = 0; j < 8; ++j) {
                float2 u = unpack2(acc[i2][j]);
                float v = half ? u.y : u.x;
                int n = tx * 8 + j;
                g_xproj[base + n] = v + bias[j0 + n];
            }
        }
    }
}

// ---------------------------------------------------------------------------
// Persistent LSTM recurrence v3 — broadcast-weight layout (crossbar-lean).
//
// 128 CTAs x 512 threads (16 warps), 1 CTA/SM. CTA cg owns 32 fused cols
// (fc = gate*8 + jj, jj in [0,8) mapping to H-col j0+jj), all 64 rows.
//
// Warp w: fcq = w&3 (8 fc: [fcq*8, fcq*8+8)), kq = w>>2 (k-split 4,
// interleaved 32-k blocks: k-block kb belongs to kq = kb%4).
// Lane l covers rows {l, l+32}. Per k:
//   w operands: ws[k][fcq*8..+8] as 4 f32x2 — LDS.128 x2, BROADCAST (all
//   lanes same address -> ~16B unique per request instead of 512B).
//   h operands: hs[row][k] (untransposed!) — LDS.128 covers 4 k per row;
//   dup2 per (row,k) on ALU pipe.
//   8 FFMA2 (2 rows x 4 fc-pairs).
// Crossbar bytes/MAC ~0.3 (was 2.5) -> smem no longer binding; FMA floor
// 16,384 cyc/step governs.
//
// SMEM: ws [1024][32] f32 (128KB, loaded once)
//       hs [2][64][132] f32 (67.5KB, double-buffered 128-k chunks; staging is
//                            straight LDG.128->STS.128, no transpose)
//       gt [64][36] f32 (9KB)
// ---------------------------------------------------------------------------
static constexpr int KCH = 128;                  // k chunk
static constexpr int NCH = H / KCH;              // 8
static constexpr int HROW = 132;                 // 128 + 4 pad
static constexpr int WS_FLOATS = H * 32;                 // 32768
static constexpr int HS_FLOATS = 2 * 64 * HROW;          // 16896
static constexpr int GT_STRIDE = 36;
static constexpr int GT_FLOATS = 64 * GT_STRIDE;         // 2304
static constexpr size_t SMEM_BYTES =
    (size_t)(WS_FLOATS + HS_FLOATS + GT_FLOATS) * 4;     // 207,872

__global__ void __launch_bounds__(NTHR, 1) lstm_persistent(
    const float* __restrict__ wh0, const float* __restrict__ wh1,
    const float* __restrict__ wh2, const float* __restrict__ wh3,
    float* __restrict__ out)
{
    extern __shared__ float smem[];
    float* ws = smem;                            // [1024][32]
    float* hs = smem + WS_FLOATS;                // [2][64][HROW]
    float* gt = smem + WS_FLOATS + HS_FLOATS;    // [64][36]
    __shared__ unsigned s_sense;

    const int tid  = threadIdx.x;
    const int cg   = blockIdx.x;
    const int j0   = cg * 8;
    const int lane = tid & 31;
    const int wrp  = tid >> 5;
    const int fcq  = wrp & 3;                    // fc quad
    const int kq   = wrp >> 2;                   // k split index

    // ---- load Wh slice into ws once: ws[k][fc] ----
    for (int idx = tid; idx < 1024 * 8; idx += NTHR) {
        int kk = idx >> 3;
        int q = idx & 7;                         // fc quad-of-4: fc = q*4..
        int gate = q >> 1;
        int jj4 = (q & 1) * 4;
        const float* __restrict__ wsel = (gate == 0) ? wh0 : (gate == 1) ? wh1
                                       : (gate == 2) ? wh2 : wh3;
        float4 v = *reinterpret_cast<const float4*>(&wsel[(size_t)kk * H + j0 + jj4]);
        *reinterpret_cast<float4*>(&ws[kk * 32 + q * 4]) = v;
    }
    if (tid == 0) s_sense = 0;
    __syncthreads();

    // pointwise ownership
    const int prow = tid >> 3;
    const int pjj = tid & 7;
    float creg = 0.0f;

    // staging mapping: 4 float4 per thread per chunk
    // idx = tid + 512*j ; row = idx>>5 ; k4 = idx&31
    for (int t = 0; t < T; ++t) {
        const float* __restrict__ hin = g_h[t & 1];
        float* __restrict__ hout = g_h[(t + 1) & 1];

        // xproj prefetch: kq==0 warps own the first gt pass
        float4 xpa[2], xpb[2];
        if (kq == 0) {
            #pragma unroll
            for (int rs = 0; rs < 2; ++rs) {
                int row = lane + rs * 32;
                size_t base = ((size_t)t * B + row) * G4H + (size_t)fcq * H + j0;
                xpa[rs] = *reinterpret_cast<const float4*>(&g_xproj[base]);
                xpb[rs] = *reinterpret_cast<const float4*>(&g_xproj[base + 4]);
            }
        }

        // stage chunk 0
        #pragma unroll
        for (int jld = 0; jld < 4; ++jld) {
            int idx = tid + 512 * jld;
            int row = idx >> 5;
            int k4 = idx & 31;
            float4 v = __ldcg(reinterpret_cast<const float4*>(&hin[row * H + k4 * 4]));
            *reinterpret_cast<float4*>(&hs[row * HROW + k4 * 4]) = v;
        }
        __syncthreads();

        ull acc[2][4];
        #pragma unroll
        for (int r = 0; r < 2; ++r)
            #pragma unroll
            for (int p = 0; p < 4; ++p) acc[r][p] = 0ULL;

        for (int c = 0; c < NCH; ++c) {
            // register-prefetch chunk c+1
            float4 pf[4];
            if (c + 1 < NCH) {
                #pragma unroll
                for (int jld = 0; jld < 4; ++jld) {
                    int idx = tid + 512 * jld;
                    int row = idx >> 5;
                    int k4 = idx & 31;
                    pf[jld] = __ldcg(reinterpret_cast<const float4*>(
                        &hin[row * H + (c + 1) * KCH + k4 * 4]));
                }
            }

            // compute this warp's 32-k window of the chunk
            const float* hb = hs + (c & 1) * (64 * HROW);
            const float* hap = hb + lane * HROW + kq * 32;
            const float* hbp = hb + (lane + 32) * HROW + kq * 32;
            const float* wsb = ws + (size_t)(c * KCH + kq * 32) * 32 + fcq * 8;

            #pragma unroll
            for (int k4 = 0; k4 < 8; ++k4) {
                float4 ha = *reinterpret_cast<const float4*>(hap + k4 * 4);
                float4 hbv = *reinterpret_cast<const float4*>(hbp + k4 * 4);
                const float* wk = wsb + k4 * 4 * 32;
                #pragma unroll
                for (int i = 0; i < 4; ++i) {
                    longlong2 w01 = *reinterpret_cast<const longlong2*>(wk + i * 32);
                    longlong2 w23 = *reinterpret_cast<const longlong2*>(wk + i * 32 + 4);
                    ull a0 = dup2((&ha.x)[i]);
                    ull a1 = dup2((&hbv.x)[i]);
                    fma2(acc[0][0], a0, (ull)w01.x);
                    fma2(acc[0][1], a0, (ull)w01.y);
                    fma2(acc[0][2], a0, (ull)w23.x);
                    fma2(acc[0][3], a0, (ull)w23.y);
                    fma2(acc[1][0], a1, (ull)w01.x);
                    fma2(acc[1][1], a1, (ull)w01.y);
                    fma2(acc[1][2], a1, (ull)w23.x);
                    fma2(acc[1][3], a1, (ull)w23.y);
                }
            }

            // commit prefetched chunk
            if (c + 1 < NCH) {
                float* hn = hs + ((c + 1) & 1) * (64 * HROW);
                #pragma unroll
                for (int jld = 0; jld < 4; ++jld) {
                    int idx = tid + 512 * jld;
                    int row = idx >> 5;
                    int k4 = idx & 31;
                    *reinterpret_cast<float4*>(&hn[row * HROW + k4 * 4]) = pf[jld];
                }
            }
            __syncthreads();
        }

        // ---- k-split(4) reduction into gt: pass p handled by kq==p warps ----
        #pragma unroll
        for (int p = 0; p < 4; ++p) {
            if (kq == p) {
                #pragma unroll
                for (int rs = 0; rs < 2; ++rs) {
                    int row = lane + rs * 32;
                    float* g = gt + row * GT_STRIDE + fcq * 8;
                    float2 u0 = unpack2(acc[rs][0]);
                    float2 u1 = unpack2(acc[rs][1]);
                    float2 u2 = unpack2(acc[rs][2]);
                    float2 u3 = unpack2(acc[rs][3]);
                    if (p == 0) {
                        float4 va = make_float4(u0.x + xpa[rs].x, u0.y + xpa[rs].y,
                                                u1.x + xpa[rs].z, u1.y + xpa[rs].w);
                        float4 vb = make_float4(u2.x + xpb[rs].x, u2.y + xpb[rs].y,
                                                u3.x + xpb[rs].z, u3.y + xpb[rs].w);
                        *reinterpret_cast<float4*>(g) = va;
                        *reinterpret_cast<float4*>(g + 4) = vb;
                    } else {
                        float4 va = *reinterpret_cast<const float4*>(g);
                        float4 vb = *reinterpret_cast<const float4*>(g + 4);
                        va.x += u0.x; va.y += u0.y; va.z += u1.x; va.w += u1.y;
                        vb.x += u2.x; vb.y += u2.y; vb.z += u3.x; vb.w += u3.y;
                        *reinterpret_cast<float4*>(g) = va;
                        *reinterpret_cast<float4*>(g + 4) = vb;
                    }
                }
            }
            __syncthreads();
        }

        // ---- pointwise LSTM cell: one element per thread ----
        {
            float gi = gt[prow * GT_STRIDE + 0 + pjj];
            float gf = gt[prow * GT_STRIDE + 8 + pjj];
            float gg = gt[prow * GT_STRIDE + 16 + pjj];
            float go = gt[prow * GT_STRIDE + 24 + pjj];
            float ig = fast_sigmoid(gi);
            float fg = fast_sigmoid(gf);
            float gv = fast_tanh(gg);
            float og = fast_sigmoid(go);
            creg = fg * creg + ig * gv;
            float hv = og * fast_tanh(creg);
            int j = j0 + pjj;
            hout[prow * H + j] = hv;
            out[((size_t)prow * T + t) * H + j] = hv;
            if (t == T - 1) {
                size_t off = (size_t)B * T * H;
                out[off + (size_t)prow * H + j] = hv;
                out[off + (size_t)B * H + (size_t)prow * H + j] = creg;
            }
        }

        // ---- grid barrier ----
        __syncthreads();
        if (tid == 0) {
            __threadfence();
            unsigned s = s_sense ^ 1u;
            s_sense = s;
            if (atomicAdd(&g_bar_count, 1u) == NCTA - 1u) {
                g_bar_count = 0;
                asm volatile("st.release.gpu.global.u32 [%0], %1;"
                             :: "l"(&g_bar_sense), "r"(s) : "memory");
            } else {
                unsigned v;
                while (true) {
                    asm volatile("ld.acquire.gpu.global.u32 %0, [%1];"
                                 : "=r"(v) : "l"(&g_bar_sense) : "memory");
                    if (v == s) break;
                    __nanosleep(32);
                }
            }
        }
        __syncthreads();
    }
}

// ---------------------------------------------------------------------------
extern "C" void kernel_launch(void* const* d_in, const int* in_sizes, int n_in,
                              void* d_out, int out_size)
{
    const float* x   = (const float*)d_in[0];
    const float* wii = (const float*)d_in[1];
    const float* whi = (const float*)d_in[2];
    const float* bi  = (const float*)d_in[3];
    const float* wif = (const float*)d_in[4];
    const float* whf = (const float*)d_in[5];
    const float* bf  = (const float*)d_in[6];
    const float* wig = (const float*)d_in[7];
    const float* whg = (const float*)d_in[8];
    const float* bg  = (const float*)d_in[9];
    const float* wio = (const float*)d_in[10];
    const float* who = (const float*)d_in[11];
    const float* bo  = (const float*)d_in[12];
    float* out = (float*)d_out;

    cudaFuncSetAttribute(lstm_persistent,
                         cudaFuncAttributeMaxDynamicSharedMemorySize,
                         (int)SMEM_BYTES);

    init_kernel<<<(B * H + 255) / 256, 256>>>();

    dim3 gx(G4H / BN, (B * T) / BM);   // (32, 256)
    xproj_kernel<<<gx, 256>>>(x, wii, wif, wig, wio, bi, bf, bg, bo);

    lstm_persistent<<<NCTA, NTHR, SMEM_BYTES>>>(whi, whf, whg, who, out);
}